// round 2
// baseline (speedup 1.0000x reference)
#include <cuda_runtime.h>
#include <math.h>

// Radon forward projection.
//   img: 512x512 fp32. Output: [A=512, D=512] fp32, flipped on both axes.
//   For each (a,d): ray from (rsx,rsy) with direction (rdx,rdy); sum S=256
//   bilinear samples (align_corners=True, zeros padding), divide by S.

#define IMG_N   512
#define N_ANG   512
#define N_DET   512
#define N_SAMP  256

__global__ __launch_bounds__(512) void radon_fwd_kernel(
    const float* __restrict__ img,
    float* __restrict__ out)
{
    const int a = blockIdx.x;     // angle index
    const int d = threadIdx.x;    // detector index

    // angle = linspace(0, pi, 512)[a] + pi/2
    const float ang = fmaf((float)a, (float)(M_PI / 511.0), (float)(M_PI / 2.0));
    float sa, ca;
    __sincosf(ang, &sa, &ca);
    // __sincosf is the fast-math version; use precise to stay close to reference
    sa = sinf(ang);
    ca = cosf(ang);

    const float SQRT2 = 1.41421356237309515f;

    // sx = linspace(-1, 1, 512)[d]   (step_size=1, distance*det_count/2 = 1)
    const float sx = fmaf((float)d, 2.0f / 511.0f, -1.0f);

    // ray start (normalized coords)
    const float rsx = fmaf(sx, ca,  SQRT2 * sa);
    const float rsy = fmaf(sx, sa, -SQRT2 * ca);
    // ray delta (end - start)
    const float rdx = -2.0f * SQRT2 * sa;
    const float rdy =  2.0f * SQRT2 * ca;

    // pixel coords: p = (g + 1) * 0.5 * (N-1) = g*255.5 + 255.5
    const float x0p = fmaf(rsx, 255.5f, 255.5f);
    const float y0p = fmaf(rsy, 255.5f, 255.5f);
    // per-step pixel delta for t = s/256
    const float dxp = rdx * (255.5f / 256.0f);
    const float dyp = rdy * (255.5f / 256.0f);

    float sum = 0.0f;

    #pragma unroll 4
    for (int s = 0; s < N_SAMP; ++s) {
        const float x = fmaf((float)s, dxp, x0p);
        const float y = fmaf((float)s, dyp, y0p);

        const float xf = floorf(x);
        const float yf = floorf(y);
        const int ix = (int)xf;
        const int iy = (int)yf;
        const float fx = x - xf;
        const float fy = y - yf;

        const float gx0 = 1.0f - fx;
        const float gy0 = 1.0f - fy;

        // per-corner validity (zeros padding)
        const bool vx0 = ((unsigned)ix       < (unsigned)IMG_N);
        const bool vx1 = ((unsigned)(ix + 1) < (unsigned)IMG_N);
        const bool vy0 = ((unsigned)iy       < (unsigned)IMG_N);
        const bool vy1 = ((unsigned)(iy + 1) < (unsigned)IMG_N);

        const int base = iy * IMG_N + ix;

        const float v00 = (vx0 && vy0) ? __ldg(img + base)             : 0.0f;
        const float v01 = (vx1 && vy0) ? __ldg(img + base + 1)         : 0.0f;
        const float v10 = (vx0 && vy1) ? __ldg(img + base + IMG_N)     : 0.0f;
        const float v11 = (vx1 && vy1) ? __ldg(img + base + IMG_N + 1) : 0.0f;

        // bilinear blend
        float top = fmaf(v01, fx, v00 * gx0);
        float bot = fmaf(v11, fx, v10 * gx0);
        sum = fmaf(top, gy0, fmaf(bot, fy, sum));
    }

    // out = flip(intens, (0,1)) ; intens[a,d] = sum / S
    out[(N_ANG - 1 - a) * N_DET + (N_DET - 1 - d)] = sum * (1.0f / (float)N_SAMP);
}

extern "C" void kernel_launch(void* const* d_in, const int* in_sizes, int n_in,
                              void* d_out, int out_size)
{
    const float* img = (const float*)d_in[0];
    float* out = (float*)d_out;
    radon_fwd_kernel<<<N_ANG, N_DET>>>(img, out);
}

// round 3
// speedup vs baseline: 2.1938x; 2.1938x over previous
#include <cuda_runtime.h>
#include <math.h>

// Radon forward projection, 512x512 img -> [512,512] sinogram (both axes flipped).
// Optimization vs R1:
//  - transposed-image gather for near-vertical detector directions (fewer L1
//    wavefronts: warp lanes stay within few image rows)
//  - angle permutation across warps for load balance (per-angle cost varies ~8x)
//  - per-ray s-range clipping (skip all-outside samples)

#define IMG_N   512
#define N_ANG   512
#define N_DET   512
#define N_SAMP  256

__device__ float g_imgT[IMG_N * IMG_N];

__global__ __launch_bounds__(256) void transpose_kernel(const float* __restrict__ img)
{
    __shared__ float tile[32][33];
    const int bx = blockIdx.x * 32;
    const int by = blockIdx.y * 32;
    const int tx = threadIdx.x;        // 0..31
    const int ty = threadIdx.y;        // 0..7
    #pragma unroll
    for (int r = 0; r < 32; r += 8)
        tile[ty + r][tx] = img[(by + ty + r) * IMG_N + (bx + tx)];
    __syncthreads();
    #pragma unroll
    for (int r = 0; r < 32; r += 8)
        g_imgT[(bx + ty + r) * IMG_N + (by + tx)] = tile[tx][ty + r];
}

__device__ __forceinline__ void clip_axis(float c0, float dc, float& lo, float& hi)
{
    const float L = -1.001f, H = (float)IMG_N + 0.001f;
    if (fabsf(dc) > 1e-9f) {
        const float t0 = (L - c0) / dc;
        const float t1 = (H - c0) / dc;
        lo = fmaxf(lo, fminf(t0, t1));
        hi = fminf(hi, fmaxf(t0, t1));
    } else if (c0 <= L || c0 >= H) {
        lo = 1.0e9f; hi = -1.0e9f;      // empty
    }
}

__global__ __launch_bounds__(512) void radon_fwd_kernel(
    const float* __restrict__ img,
    float* __restrict__ out)
{
    const int widx = threadIdx.x >> 5;
    const int lane = threadIdx.x & 31;
    const int wg   = blockIdx.x * 16 + widx;        // 0..8191

    // angle permutation: each block mixes 16 well-spread angles
    const int a     = (wg * 341) & 511;             // gcd(341,512)=1 -> bijection
    const int chunk = wg >> 9;                      // 0..15
    const int d     = chunk * 32 + lane;            // detector

    const float ang = fmaf((float)a, (float)(M_PI / 511.0), (float)(M_PI / 2.0));
    const float sa = sinf(ang);
    const float ca = cosf(ang);

    const float SQRT2 = 1.41421356237309515f;
    const float sx = fmaf((float)d, 2.0f / 511.0f, -1.0f);

    // ray start / delta in normalized coords
    const float rsx = fmaf(sx, ca,  SQRT2 * sa);
    const float rsy = fmaf(sx, sa, -SQRT2 * ca);
    const float rdx = -2.0f * SQRT2 * sa;
    const float rdy =  2.0f * SQRT2 * ca;

    // pixel coords: p = g*255.5 + 255.5 ; per-step delta for t = s/256
    float x0p = fmaf(rsx, 255.5f, 255.5f);
    float y0p = fmaf(rsy, 255.5f, 255.5f);
    float dxp = rdx * (255.5f / 256.0f);
    float dyp = rdy * (255.5f / 256.0f);

    // Warp-uniform orientation choice: lanes (detectors) spread along (ca, sa).
    // If |sa| > |ca| the spread is mostly across image rows -> sample the
    // transposed image with swapped coords instead (bilinear is swap-symmetric).
    const float* src = img;
    if (fabsf(sa) > fabsf(ca)) {
        src = g_imgT;
        float t;
        t = x0p; x0p = y0p; y0p = t;
        t = dxp; dxp = dyp; dyp = t;
    }

    // clip sample range to the (slightly widened) image box
    float lo = 0.0f, hi = (float)(N_SAMP - 1);
    clip_axis(x0p, dxp, lo, hi);
    clip_axis(y0p, dyp, lo, hi);
    int s0 = (lo > 0.0f) ? (int)ceilf(lo) : 0;
    int s1 = (hi < (float)(N_SAMP - 1)) ? (int)floorf(hi) : (N_SAMP - 1);

    float sum = 0.0f;

    #pragma unroll 4
    for (int s = s0; s <= s1; ++s) {
        const float x = fmaf((float)s, dxp, x0p);
        const float y = fmaf((float)s, dyp, y0p);

        const float xf = floorf(x);
        const float yf = floorf(y);
        const int ix = (int)xf;
        const int iy = (int)yf;
        const float fx = x - xf;
        const float fy = y - yf;

        const float gx0 = 1.0f - fx;
        const float gy0 = 1.0f - fy;

        const bool vx0 = ((unsigned)ix       < (unsigned)IMG_N);
        const bool vx1 = ((unsigned)(ix + 1) < (unsigned)IMG_N);
        const bool vy0 = ((unsigned)iy       < (unsigned)IMG_N);
        const bool vy1 = ((unsigned)(iy + 1) < (unsigned)IMG_N);

        const int base = iy * IMG_N + ix;

        const float v00 = (vx0 && vy0) ? __ldg(src + base)             : 0.0f;
        const float v01 = (vx1 && vy0) ? __ldg(src + base + 1)         : 0.0f;
        const float v10 = (vx0 && vy1) ? __ldg(src + base + IMG_N)     : 0.0f;
        const float v11 = (vx1 && vy1) ? __ldg(src + base + IMG_N + 1) : 0.0f;

        const float top = fmaf(v01, fx, v00 * gx0);
        const float bot = fmaf(v11, fx, v10 * gx0);
        sum = fmaf(top, gy0, fmaf(bot, fy, sum));
    }

    out[(N_ANG - 1 - a) * N_DET + (N_DET - 1 - d)] = sum * (1.0f / (float)N_SAMP);
}

extern "C" void kernel_launch(void* const* d_in, const int* in_sizes, int n_in,
                              void* d_out, int out_size)
{
    const float* img = (const float*)d_in[0];
    float* out = (float*)d_out;

    dim3 tb(32, 8);
    dim3 tg(IMG_N / 32, IMG_N / 32);
    transpose_kernel<<<tg, tb>>>(img);

    radon_fwd_kernel<<<N_ANG, N_DET>>>(img, out);
}

// round 4
// speedup vs baseline: 2.9659x; 1.3519x over previous
#include <cuda_runtime.h>
#include <math.h>

// Radon forward projection, 512x512 img -> [512,512] sinogram (both axes flipped).
// R3: padded float2 lookup tables (2 LDG.64/sample, zero boundary predicates),
//     transposed twin for near-vertical detector directions, s-split x2 with
//     atomicAdd for full-chip occupancy, angle permutation for balance.

#define IMG_N   512
#define N_ANG   512
#define N_DET   512
#define N_SAMP  256

#define PAD     3
#define TW      (IMG_N + 2*PAD + 2)     // 520 table width/height

__device__ float2 g_tab [TW * TW];      // P[py][px] = (z(py-3,px-3), z(py-3,px-2))
__device__ float2 g_tabT[TW * TW];      // same for transposed image

__global__ __launch_bounds__(256) void build_tables(const float* __restrict__ img)
{
    const int idx = blockIdx.x * 256 + threadIdx.x;
    if (idx >= TW * TW) return;
    const int py = idx / TW, px = idx % TW;
    const int r = py - PAD, c = px - PAD;

    const bool rv = ((unsigned)r < (unsigned)IMG_N);
    const bool c0v = ((unsigned)c < (unsigned)IMG_N);
    const bool c1v = ((unsigned)(c + 1) < (unsigned)IMG_N);

    float a0 = (rv && c0v) ? img[r * IMG_N + c]       : 0.0f;
    float a1 = (rv && c1v) ? img[r * IMG_N + c + 1]   : 0.0f;
    g_tab[idx] = make_float2(a0, a1);

    // transposed image: zT(r,c) = z(c,r)
    float b0 = (rv && c0v) ? img[c * IMG_N + r]       : 0.0f;
    float b1 = (rv && c1v) ? img[(c + 1) * IMG_N + r] : 0.0f;
    g_tabT[idx] = make_float2(b0, b1);
}

__device__ __forceinline__ void clip_axis(float c0, float dc, float& lo, float& hi)
{
    // shifted pixel coords; keep x' in [1, TW-3] => unshifted in [-2, 514]
    const float L = 1.0f, H = (float)(TW - 3);
    if (fabsf(dc) > 1e-9f) {
        const float t0 = (L - c0) / dc;
        const float t1 = (H - c0) / dc;
        lo = fmaxf(lo, fminf(t0, t1));
        hi = fminf(hi, fmaxf(t0, t1));
    } else if (c0 <= L || c0 >= H) {
        lo = 1.0e9f; hi = -1.0e9f;      // empty
    }
}

__global__ __launch_bounds__(256) void radon_fwd_kernel(float* __restrict__ out)
{
    const int widx = threadIdx.x >> 5;
    const int lane = threadIdx.x & 31;
    const int wg   = blockIdx.x * 8 + widx;   // 0..16383

    const int h   = wg & 1;                   // s-half
    const int rid = wg >> 1;                  // 0..8191  (ray-warp id)

    // angle permutation for load balance (gcd(341,512)=1 -> bijection)
    const int a     = (rid * 341) & 511;
    const int chunk = rid >> 9;               // 0..15
    const int d     = chunk * 32 + lane;      // detector

    const float ang = fmaf((float)a, (float)(M_PI / 511.0), (float)(M_PI / 2.0));
    const float sa = sinf(ang);
    const float ca = cosf(ang);

    const float SQRT2 = 1.41421356237309515f;
    const float sx = fmaf((float)d, 2.0f / 511.0f, -1.0f);

    // ray start / delta, normalized coords
    const float rsx = fmaf(sx, ca,  SQRT2 * sa);
    const float rsy = fmaf(sx, sa, -SQRT2 * ca);
    const float rdx = -2.0f * SQRT2 * sa;
    const float rdy =  2.0f * SQRT2 * ca;

    // shifted pixel coords: p = g*255.5 + 255.5 + PAD ; step delta for t=s/256
    float x0p = fmaf(rsx, 255.5f, 255.5f + (float)PAD);
    float y0p = fmaf(rsy, 255.5f, 255.5f + (float)PAD);
    float dxp = rdx * (255.5f / 256.0f);
    float dyp = rdy * (255.5f / 256.0f);

    // warp-uniform: pick the orientation where lanes stay within fewer rows
    const float2* src = g_tab;
    if (fabsf(sa) > fabsf(ca)) {
        src = g_tabT;
        float t;
        t = x0p; x0p = y0p; y0p = t;
        t = dxp; dxp = dyp; dyp = t;
    }

    // clip sample range to table interior
    float lo = 0.0f, hi = (float)(N_SAMP - 1);
    clip_axis(x0p, dxp, lo, hi);
    clip_axis(y0p, dyp, lo, hi);
    int s0 = (lo > 0.0f) ? (int)ceilf(lo) : 0;
    int s1 = (hi < (float)(N_SAMP - 1)) ? (int)floorf(hi) : (N_SAMP - 1);

    // restrict to this warp's half
    const int hs0 = h * (N_SAMP / 2);
    const int hs1 = hs0 + (N_SAMP / 2) - 1;
    s0 = max(s0, hs0);
    s1 = min(s1, hs1);
    if (s0 > s1) return;                      // out already zero-initialized

    float sum = 0.0f;

    #pragma unroll 4
    for (int s = s0; s <= s1; ++s) {
        const float x = fmaf((float)s, dxp, x0p);
        const float y = fmaf((float)s, dyp, y0p);

        const float xf = floorf(x);
        const float yf = floorf(y);
        const float fx = x - xf;
        const float fy = y - yf;

        const int base = (int)yf * TW + (int)xf;

        const float2 t = __ldg(src + base);
        const float2 b = __ldg(src + base + TW);

        const float top = fmaf(fx, t.y - t.x, t.x);
        const float bot = fmaf(fx, b.y - b.x, b.x);
        sum += fmaf(fy, bot - top, top);
    }

    const int o = (N_ANG - 1 - a) * N_DET + (N_DET - 1 - d);
    atomicAdd(out + o, sum * (1.0f / (float)N_SAMP));
}

extern "C" void kernel_launch(void* const* d_in, const int* in_sizes, int n_in,
                              void* d_out, int out_size)
{
    const float* img = (const float*)d_in[0];
    float* out = (float*)d_out;

    cudaMemsetAsync(out, 0, N_ANG * N_DET * sizeof(float));

    build_tables<<<(TW * TW + 255) / 256, 256>>>(img);

    // 512 angles * 16 det-warps * 2 s-halves = 16384 warps = 2048 blocks of 256
    radon_fwd_kernel<<<2048, 256>>>(out);
}

// round 5
// speedup vs baseline: 3.5149x; 1.1851x over previous
#include <cuda_runtime.h>
#include <math.h>

// Radon forward projection, 512x512 img -> [512,512] sinogram (both axes flipped).
// R4: float4 QUAD tables — each entry packs the full 2x2 bilinear footprint,
//     so the inner loop does ONE aligned LDG.128 per sample (row-scatter
//     wavefronts charged once instead of twice). Plus: transposed twin for
//     near-vertical detector directions, s-split x2 + atomicAdd for occupancy,
//     angle permutation for balance, per-ray s-range clipping.

#define IMG_N   512
#define N_ANG   512
#define N_DET   512
#define N_SAMP  256

#define PAD     3
#define TW      (IMG_N + 2*PAD + 2)     // 520

// P4[py][px] = (z(r,c), z(r,c+1), z(r+1,c), z(r+1,c+1)),  r=py-PAD, c=px-PAD
__device__ float4 g_tab [TW * TW];
__device__ float4 g_tabT[TW * TW];      // same for transposed image

__global__ __launch_bounds__(256) void build_tables(const float* __restrict__ img)
{
    const int idx = blockIdx.x * 256 + threadIdx.x;
    if (idx >= TW * TW) return;
    const int py = idx / TW, px = idx % TW;
    const int r = py - PAD, c = px - PAD;

    const bool r0 = ((unsigned)r       < (unsigned)IMG_N);
    const bool r1 = ((unsigned)(r + 1) < (unsigned)IMG_N);
    const bool c0 = ((unsigned)c       < (unsigned)IMG_N);
    const bool c1 = ((unsigned)(c + 1) < (unsigned)IMG_N);

    float4 q;
    q.x = (r0 && c0) ? img[r * IMG_N + c]             : 0.0f;
    q.y = (r0 && c1) ? img[r * IMG_N + c + 1]         : 0.0f;
    q.z = (r1 && c0) ? img[(r + 1) * IMG_N + c]       : 0.0f;
    q.w = (r1 && c1) ? img[(r + 1) * IMG_N + c + 1]   : 0.0f;
    g_tab[idx] = q;

    // transposed image: zT(r,c) = z(c,r)
    float4 t;
    t.x = (r0 && c0) ? img[c * IMG_N + r]             : 0.0f;
    t.y = (r0 && c1) ? img[(c + 1) * IMG_N + r]       : 0.0f;
    t.z = (r1 && c0) ? img[c * IMG_N + r + 1]         : 0.0f;
    t.w = (r1 && c1) ? img[(c + 1) * IMG_N + r + 1]   : 0.0f;
    g_tabT[idx] = t;
}

__device__ __forceinline__ void clip_axis(float c0, float dc, float& lo, float& hi)
{
    // shifted pixel coords; keep x' in [1, TW-3]
    const float L = 1.0f, H = (float)(TW - 3);
    if (fabsf(dc) > 1e-9f) {
        const float t0 = (L - c0) / dc;
        const float t1 = (H - c0) / dc;
        lo = fmaxf(lo, fminf(t0, t1));
        hi = fminf(hi, fmaxf(t0, t1));
    } else if (c0 <= L || c0 >= H) {
        lo = 1.0e9f; hi = -1.0e9f;      // empty
    }
}

__global__ __launch_bounds__(256) void radon_fwd_kernel(float* __restrict__ out)
{
    const int widx = threadIdx.x >> 5;
    const int lane = threadIdx.x & 31;
    const int wg   = blockIdx.x * 8 + widx;   // 0..16383

    const int h   = wg & 1;                   // s-half
    const int rid = wg >> 1;                  // 0..8191

    // angle permutation for load balance (gcd(341,512)=1 -> bijection)
    const int a     = (rid * 341) & 511;
    const int chunk = rid >> 9;               // 0..15
    const int d     = chunk * 32 + lane;      // detector

    const float ang = fmaf((float)a, (float)(M_PI / 511.0), (float)(M_PI / 2.0));
    const float sa = sinf(ang);
    const float ca = cosf(ang);

    const float SQRT2 = 1.41421356237309515f;
    const float sx = fmaf((float)d, 2.0f / 511.0f, -1.0f);

    const float rsx = fmaf(sx, ca,  SQRT2 * sa);
    const float rsy = fmaf(sx, sa, -SQRT2 * ca);
    const float rdx = -2.0f * SQRT2 * sa;
    const float rdy =  2.0f * SQRT2 * ca;

    // shifted pixel coords: p = g*255.5 + 255.5 + PAD ; step delta for t=s/256
    float x0p = fmaf(rsx, 255.5f, 255.5f + (float)PAD);
    float y0p = fmaf(rsy, 255.5f, 255.5f + (float)PAD);
    float dxp = rdx * (255.5f / 256.0f);
    float dyp = rdy * (255.5f / 256.0f);

    // warp-uniform orientation: minimize cross-row scatter of the 32 lanes
    const float4* src = g_tab;
    if (fabsf(sa) > fabsf(ca)) {
        src = g_tabT;
        float t;
        t = x0p; x0p = y0p; y0p = t;
        t = dxp; dxp = dyp; dyp = t;
    }

    // clip sample range to table interior
    float lo = 0.0f, hi = (float)(N_SAMP - 1);
    clip_axis(x0p, dxp, lo, hi);
    clip_axis(y0p, dyp, lo, hi);
    int s0 = (lo > 0.0f) ? (int)ceilf(lo) : 0;
    int s1 = (hi < (float)(N_SAMP - 1)) ? (int)floorf(hi) : (N_SAMP - 1);

    // restrict to this warp's s-half
    const int hs0 = h * (N_SAMP / 2);
    const int hs1 = hs0 + (N_SAMP / 2) - 1;
    s0 = max(s0, hs0);
    s1 = min(s1, hs1);
    if (s0 > s1) return;                      // out already zeroed

    float sum = 0.0f;

    #pragma unroll 4
    for (int s = s0; s <= s1; ++s) {
        const float x = fmaf((float)s, dxp, x0p);
        const float y = fmaf((float)s, dyp, y0p);

        const float xf = floorf(x);
        const float yf = floorf(y);
        const float fx = x - xf;
        const float fy = y - yf;

        const float4 q = __ldg(src + (int)yf * TW + (int)xf);

        const float top = fmaf(fx, q.y - q.x, q.x);
        const float bot = fmaf(fx, q.w - q.z, q.z);
        sum += fmaf(fy, bot - top, top);
    }

    const int o = (N_ANG - 1 - a) * N_DET + (N_DET - 1 - d);
    atomicAdd(out + o, sum * (1.0f / (float)N_SAMP));
}

extern "C" void kernel_launch(void* const* d_in, const int* in_sizes, int n_in,
                              void* d_out, int out_size)
{
    const float* img = (const float*)d_in[0];
    float* out = (float*)d_out;

    cudaMemsetAsync(out, 0, N_ANG * N_DET * sizeof(float));

    build_tables<<<(TW * TW + 255) / 256, 256>>>(img);

    // 512 angles * 16 det-warps * 2 s-halves = 16384 warps = 2048 blocks of 256
    radon_fwd_kernel<<<2048, 256>>>(out);
}